// round 16
// baseline (speedup 1.0000x reference)
#include <cuda_runtime.h>
#include <cuda_bf16.h>
#include <math.h>

#define NMAX 200000
#define EMAX 600000
#define BMAX 10000
#define D 128

typedef unsigned short ushort_t;

// ---------------- scratch ----------------
__device__ float g_xh[NMAX * D];
__device__ float g_xt[NMAX * D];
__device__ float g_tmp[NMAX * D];
__device__ float g_acc[NMAX * D];
__device__ float g_tmp2[NMAX * D];
__device__ float g_acc2[NMAX * D];
__device__ float g_tmp3[NMAX * D];
__device__ float g_tmp4[NMAX * D];
__device__ float g_alS[NMAX * 2],  g_alD[NMAX * 2],  g_s[NMAX * 2];
__device__ float g_alS2[NMAX * 2], g_alD2[NMAX * 2], g_s2[NMAX * 2];
__device__ float g_alS3[NMAX], g_s3[NMAX];
__device__ float g_alS4[NMAX], g_s4[NMAX];
__device__ float g_alDit_h[NMAX], g_alDit_t[NMAX];
__device__ float g_ew[EMAX], g_ew2[EMAX];
__device__ float g_vdst[D];
__device__ float g_sB[BMAX], g_sB2[BMAX];
__device__ ushort_t g_w_h[576 * 128], g_w_l[576 * 128];

// ---------------- helpers ----------------
__device__ __forceinline__ float lrelu(float x) { return x > 0.f ? x : 0.2f * x; }

__device__ __forceinline__ float warp_sum(float v) {
#pragma unroll
    for (int o = 16; o > 0; o >>= 1) v += __shfl_xor_sync(0xffffffffu, v, o);
    return v;
}

__device__ __forceinline__ void mma_bf16(float* c, const unsigned* a, const unsigned* b) {
    asm volatile(
        "mma.sync.aligned.m16n8k16.row.col.f32.bf16.bf16.f32 "
        "{%0,%1,%2,%3}, {%4,%5,%6,%7}, {%8,%9}, {%0,%1,%2,%3};"
        : "+f"(c[0]), "+f"(c[1]), "+f"(c[2]), "+f"(c[3])
        : "r"(a[0]), "r"(a[1]), "r"(a[2]), "r"(a[3]), "r"(b[0]), "r"(b[1]));
}

__device__ __forceinline__ void ldsm4(unsigned* r, const void* p) {
    unsigned addr = (unsigned)__cvta_generic_to_shared(p);
    asm volatile("ldmatrix.sync.aligned.m8n8.x4.shared.b16 {%0,%1,%2,%3}, [%4];"
                 : "=r"(r[0]), "=r"(r[1]), "=r"(r[2]), "=r"(r[3]) : "r"(addr));
}

__device__ __forceinline__ void ldsm4t(unsigned* r, const void* p) {
    unsigned addr = (unsigned)__cvta_generic_to_shared(p);
    asm volatile("ldmatrix.sync.aligned.m8n8.x4.trans.shared.b16 {%0,%1,%2,%3}, [%4];"
                 : "=r"(r[0]), "=r"(r[1]), "=r"(r[2]), "=r"(r[3]) : "r"(addr));
}

__device__ __forceinline__ void redAdd4(float* p, float x, float y, float z, float w) {
    asm volatile("red.global.add.v4.f32 [%0], {%1,%2,%3,%4};"
                 :: "l"(p), "f"(x), "f"(y), "f"(z), "f"(w) : "memory");
}

__device__ __forceinline__ void split1(float a, ushort_t& h, ushort_t& l) {
    __nv_bfloat16 ah = __float2bfloat16(a);
    h = __bfloat16_as_ushort(ah);
    l = __bfloat16_as_ushort(__float2bfloat16(a - __bfloat162float(ah)));
}

__device__ __forceinline__ void split2(float a, float b, unsigned& hi, unsigned& lo) {
    ushort_t ha, la, hb, lb;
    split1(a, ha, la);
    split1(b, hb, lb);
    hi = (unsigned)ha | ((unsigned)hb << 16);
    lo = (unsigned)la | ((unsigned)lb << 16);
}

// ---------------- single-launch weight split ----------------
__global__ void split_all(const float* __restrict__ Wg, const float* __restrict__ Wi,
                          const float* __restrict__ Ws, const float* __restrict__ Wr,
                          ushort_t* __restrict__ H, ushort_t* __restrict__ L) {
    int i = blockIdx.x * blockDim.x + threadIdx.x;
    if (i >= 576 * 128 / 4) return;
    int base = i * 4;
    const float* src;
    int off;
    if (base < 64 * 128)        { src = Wg; off = base; }
    else if (base < 192 * 128)  { src = Wi; off = base - 64 * 128; }
    else if (base < 320 * 128)  { src = Ws; off = base - 192 * 128; }
    else                        { src = Wr; off = base - 320 * 128; }
    float4 v = *reinterpret_cast<const float4*>(src + off);
    unsigned h01, l01, h23, l23;
    split2(v.x, v.y, h01, l01);
    split2(v.z, v.w, h23, l23);
    *reinterpret_cast<uint2*>(H + base) = make_uint2(h01, h23);
    *reinterpret_cast<uint2*>(L + base) = make_uint2(l01, l23);
}

// ---------------- bf16x3 GEMM with fused node-prep epilogue + companion zero-fill ----
// MODE 0: plain.  MODE 1: 2-head prep.  MODE 2: 1-head both dots.
// MODE 3: 1-head aS only.  MODE 4: SAG prep.
// Z (optional): companion accumulator buffer zeroed over the same [n x 128] space.
template <int K, int MODE>
__global__ void __launch_bounds__(256, 2)
gemm_bf3(const float* __restrict__ A0, const float* __restrict__ A1,
         const ushort_t* __restrict__ Wh, const ushort_t* __restrict__ Wl,
         const float* __restrict__ bias, float* __restrict__ C, int n,
         const float* __restrict__ aS, const float* __restrict__ aD,
         float* __restrict__ oS, float* __restrict__ oD,
         float* __restrict__ sArr, const float* __restrict__ brel,
         float* __restrict__ Z) {
    __shared__ __align__(16) ushort_t sAh[128][40], sAl[128][40];
    __shared__ __align__(16) ushort_t sBh[32][136], sBl[32][136];
    __shared__ float sRed[128][2][2];
    const int row0 = blockIdx.x * 128;
    const int tid = threadIdx.x;
    const int warp = tid >> 5, lane = tid & 31;
    const int wm = warp >> 1, wn = warp & 1;
    const int g = lane >> 2, tig = lane & 3;
    const int l15 = lane & 15, l16o = ((lane >> 4) & 1) * 8;

    float acc[2][8][4];
#pragma unroll
    for (int mt = 0; mt < 2; mt++)
#pragma unroll
        for (int nt = 0; nt < 8; nt++)
#pragma unroll
            for (int v = 0; v < 4; v++) acc[mt][nt][v] = 0.f;

    for (int k0 = 0; k0 < K; k0 += 32) {
        const float* Abase;
        int kloc, stride;
        if (K == 256) { Abase = (k0 < 128) ? A0 : A1; kloc = k0 & 127; stride = 128; }
        else          { Abase = A0; kloc = k0; stride = K; }
#pragma unroll
        for (int i = 0; i < 4; i++) {
            int L = i * 256 + tid;
            int r = L >> 3, kc = (L & 7) << 2;
            float4 v = make_float4(0.f, 0.f, 0.f, 0.f);
            int gr = row0 + r;
            if (gr < n) v = *reinterpret_cast<const float4*>(Abase + (size_t)gr * stride + kloc + kc);
            unsigned h01, l01, h23, l23;
            split2(v.x, v.y, h01, l01);
            split2(v.z, v.w, h23, l23);
            *reinterpret_cast<uint2*>(&sAh[r][kc]) = make_uint2(h01, h23);
            *reinterpret_cast<uint2*>(&sAl[r][kc]) = make_uint2(l01, l23);
        }
#pragma unroll
        for (int i = 0; i < 2; i++) {
            int L = i * 256 + tid;
            int r = L >> 4, c8 = (L & 15) * 8;
            *reinterpret_cast<uint4*>(&sBh[r][c8]) =
                *reinterpret_cast<const uint4*>(Wh + (size_t)(k0 + r) * D + c8);
            *reinterpret_cast<uint4*>(&sBl[r][c8]) =
                *reinterpret_cast<const uint4*>(Wl + (size_t)(k0 + r) * D + c8);
        }
        __syncthreads();
#pragma unroll
        for (int kk = 0; kk < 32; kk += 16) {
            unsigned ah[2][4], al[2][4];
#pragma unroll
            for (int mt = 0; mt < 2; mt++) {
                int ar = wm * 32 + mt * 16 + l15;
                ldsm4(ah[mt], &sAh[ar][kk + l16o]);
                ldsm4(al[mt], &sAl[ar][kk + l16o]);
            }
            int br = kk + l15;
#pragma unroll
            for (int h2 = 0; h2 < 2; h2++) {
                unsigned bh[4][2], bl[4][2], t4[4];
#pragma unroll
                for (int p = 0; p < 2; p++) {
                    int bc = wn * 64 + h2 * 32 + p * 16 + l16o;
                    ldsm4t(t4, &sBh[br][bc]);
                    bh[2 * p][0] = t4[0]; bh[2 * p][1] = t4[1];
                    bh[2 * p + 1][0] = t4[2]; bh[2 * p + 1][1] = t4[3];
                    ldsm4t(t4, &sBl[br][bc]);
                    bl[2 * p][0] = t4[0]; bl[2 * p][1] = t4[1];
                    bl[2 * p + 1][0] = t4[2]; bl[2 * p + 1][1] = t4[3];
                }
#pragma unroll
                for (int mt = 0; mt < 2; mt++)
#pragma unroll
                    for (int nt = 0; nt < 4; nt++) {
                        float* c = acc[mt][h2 * 4 + nt];
                        mma_bf16(c, al[mt], bh[nt]);
                        mma_bf16(c, ah[mt], bl[nt]);
                        mma_bf16(c, ah[mt], bh[nt]);
                    }
            }
        }
        __syncthreads();
    }

    float pS[4] = {0.f, 0.f, 0.f, 0.f};
    float pD[4] = {0.f, 0.f, 0.f, 0.f};

#pragma unroll
    for (int mt = 0; mt < 2; mt++) {
        int r0 = row0 + wm * 32 + mt * 16 + g;
        int r1 = r0 + 8;
#pragma unroll
        for (int nt = 0; nt < 8; nt++) {
            int c = wn * 64 + nt * 8 + 2 * tig;
            float b0 = 0.f, b1 = 0.f;
            if (bias) { b0 = __ldg(bias + c); b1 = __ldg(bias + c + 1); }
            float v0 = acc[mt][nt][0] + b0, v1 = acc[mt][nt][1] + b1;
            float v2 = acc[mt][nt][2] + b0, v3 = acc[mt][nt][3] + b1;
            if (MODE) {
                float a0 = __ldg(aS + c), a1 = __ldg(aS + c + 1);
                pS[mt * 2 + 0] += v0 * a0 + v1 * a1;
                pS[mt * 2 + 1] += v2 * a0 + v3 * a1;
                if (MODE != 3) {
                    float d0 = __ldg(aD + c), d1 = __ldg(aD + c + 1);
                    pD[mt * 2 + 0] += v0 * d0 + v1 * d1;
                    pD[mt * 2 + 1] += v2 * d0 + v3 * d1;
                }
            }
            if (r0 < n) {
                float* cp = C + (size_t)r0 * D + c;
                cp[0] = v0; cp[1] = v1;
                if (Z) { float* zp = Z + (size_t)r0 * D + c; zp[0] = 0.f; zp[1] = 0.f; }
            }
            if (r1 < n) {
                float* cp = C + (size_t)r1 * D + c;
                cp[0] = v2; cp[1] = v3;
                if (Z) { float* zp = Z + (size_t)r1 * D + c; zp[0] = 0.f; zp[1] = 0.f; }
            }
        }
    }

    if (MODE) {
#pragma unroll
        for (int i = 0; i < 4; i++) {
            pS[i] += __shfl_down_sync(0xffffffffu, pS[i], 2);
            pS[i] += __shfl_down_sync(0xffffffffu, pS[i], 1);
            if (MODE != 3) {
                pD[i] += __shfl_down_sync(0xffffffffu, pD[i], 2);
                pD[i] += __shfl_down_sync(0xffffffffu, pD[i], 1);
            }
        }
        if (MODE == 1) {
            if (tig == 0) {
#pragma unroll
                for (int i = 0; i < 4; i++) {
                    int r = wm * 32 + (i >> 1) * 16 + g + (i & 1) * 8;
                    int gr = row0 + r;
                    if (gr < n) {
                        oS[gr * 2 + wn] = pS[i];
                        oD[gr * 2 + wn] = pD[i];
                        sArr[gr * 2 + wn] = 0.f;
                    }
                }
            }
        } else {
            if (tig == 0) {
#pragma unroll
                for (int i = 0; i < 4; i++) {
                    int r = wm * 32 + (i >> 1) * 16 + g + (i & 1) * 8;
                    sRed[r][0][wn] = pS[i];
                    if (MODE != 3) sRed[r][1][wn] = pD[i];
                }
            }
            __syncthreads();
            if (tid < 128) {
                int gr = row0 + tid;
                if (gr < n) {
                    float S = sRed[tid][0][0] + sRed[tid][0][1];
                    oS[gr] = S;
                    if (MODE == 2) {
                        oD[gr] = sRed[tid][1][0] + sRed[tid][1][1];
                        sArr[gr] = 0.f;
                    } else if (MODE == 3) {
                        sArr[gr] = 0.f;
                    } else {
                        oD[gr] = sRed[tid][1][0] + sRed[tid][1][1] + __ldg(brel);
                    }
                }
            }
        }
    }
}

// ---------------- edge aggregate (R13 config): 8 lanes/edge, 2 float4, w-cached A/B ----
__global__ void edge_agg2_a(const int* __restrict__ src, const int* __restrict__ dst,
                            const float* __restrict__ alS, const float* __restrict__ alD,
                            float* s, const float* __restrict__ xs, float* acc,
                            float* __restrict__ ew, int E) {
    int t = blockIdx.x * blockDim.x + threadIdx.x;
    int e = t >> 3;
    if (e >= E) return;
    int lane = threadIdx.x & 31;
    int sub = lane & 7, base = lane & ~7;
    int u = 0, v = 0;
    if (sub == 0) { u = src[e]; v = dst[e]; }
    u = __shfl_sync(0xffffffffu, u, base);
    v = __shfl_sync(0xffffffffu, v, base);
    float w0 = 0.f;
    if (sub == 0) {
        float2 aS = *reinterpret_cast<const float2*>(alS + u * 2);
        float2 aD = *reinterpret_cast<const float2*>(alD + v * 2);
        w0 = __expf(lrelu(aS.x + aD.x));
        float w1 = __expf(lrelu(aS.y + aD.y));
        atomicAdd(&s[v * 2 + 0], w0);
        atomicAdd(&s[v * 2 + 1], w1);
        ew[e] = w1;
    }
    w0 = __shfl_sync(0xffffffffu, w0, base);
    int c = sub * 4;
    const float* xp = xs + (size_t)u * D;
    float4 x0 = *reinterpret_cast<const float4*>(xp + c);
    float4 x1 = *reinterpret_cast<const float4*>(xp + c + 32);
    float* ap = acc + (size_t)v * D;
    redAdd4(ap + c,      w0 * x0.x, w0 * x0.y, w0 * x0.z, w0 * x0.w);
    redAdd4(ap + c + 32, w0 * x1.x, w0 * x1.y, w0 * x1.z, w0 * x1.w);
}

__global__ void edge_agg_b(const int* __restrict__ src, const int* __restrict__ dst,
                           const float* __restrict__ ew, const float* __restrict__ xs,
                           float* acc, int E) {
    int t = blockIdx.x * blockDim.x + threadIdx.x;
    int e = t >> 3;
    if (e >= E) return;
    int lane = threadIdx.x & 31;
    int sub = lane & 7, base = lane & ~7;
    int u = 0, v = 0;
    if (sub == 0) { u = src[e]; v = dst[e]; }
    u = __shfl_sync(0xffffffffu, u, base);
    v = __shfl_sync(0xffffffffu, v, base);
    float w = ew[e];
    int c = 64 + sub * 4;
    const float* xp = xs + (size_t)u * D;
    float4 x0 = *reinterpret_cast<const float4*>(xp + c);
    float4 x1 = *reinterpret_cast<const float4*>(xp + c + 32);
    float* ap = acc + (size_t)v * D;
    redAdd4(ap + c,      w * x0.x, w * x0.y, w * x0.z, w * x0.w);
    redAdd4(ap + c + 32, w * x1.x, w * x1.y, w * x1.z, w * x1.w);
}

__global__ void edge_agg1_a(const int* __restrict__ src, const int* __restrict__ dst,
                            const float* __restrict__ alS, const float* __restrict__ alD,
                            float* s, const float* __restrict__ xs, float* acc,
                            float* __restrict__ ew, int E) {
    int t = blockIdx.x * blockDim.x + threadIdx.x;
    int e = t >> 3;
    if (e >= E) return;
    int lane = threadIdx.x & 31;
    int sub = lane & 7, base = lane & ~7;
    int u = 0, v = 0;
    if (sub == 0) { u = src[e]; v = dst[e]; }
    u = __shfl_sync(0xffffffffu, u, base);
    v = __shfl_sync(0xffffffffu, v, base);
    float w = 0.f;
    if (sub == 0) {
        w = __expf(lrelu(alS[u] + alD[v]));
        atomicAdd(&s[v], w);
        ew[e] = w;
    }
    w = __shfl_sync(0xffffffffu, w, base);
    int c = sub * 4;
    const float* xp = xs + (size_t)u * D;
    float4 x0 = *reinterpret_cast<const float4*>(xp + c);
    float4 x1 = *reinterpret_cast<const float4*>(xp + c + 32);
    float* ap = acc + (size_t)v * D;
    redAdd4(ap + c,      w * x0.x, w * x0.y, w * x0.z, w * x0.w);
    redAdd4(ap + c + 32, w * x1.x, w * x1.y, w * x1.z, w * x1.w);
}

// ---------------- finalize stage 1 (+ fused inter dst-logit) ----------------
__global__ void fin_stage1(const float* __restrict__ acc, const float* __restrict__ xs,
                           const float* __restrict__ alS, const float* __restrict__ alD,
                           const float* __restrict__ s,
                           const float* __restrict__ bgat, const float* __restrict__ g,
                           const float* __restrict__ bb, float* __restrict__ out,
                           const float* __restrict__ vdst, float* __restrict__ alDit,
                           int n) {
    int warp = (blockIdx.x * blockDim.x + threadIdx.x) >> 5;
    int lane = threadIdx.x & 31;
    if (warp >= n) return;
    int h = lane >> 4;
    int c = lane * 4;
    float e  = lrelu(alS[warp * 2 + h] + alD[warp * 2 + h]);
    float ws = __expf(e);
    float inv = 1.f / (s[warp * 2 + h] + ws + 1e-16f);
    float4 A = *reinterpret_cast<const float4*>(acc + (size_t)warp * D + c);
    float4 X = *reinterpret_cast<const float4*>(xs + (size_t)warp * D + c);
    float4 Bt = *reinterpret_cast<const float4*>(bgat + c);
    float4 val;
    val.x = (A.x + ws * X.x) * inv + Bt.x;
    val.y = (A.y + ws * X.y) * inv + Bt.y;
    val.z = (A.z + ws * X.z) * inv + Bt.z;
    val.w = (A.w + ws * X.w) * inv + Bt.w;
    float sum = warp_sum(val.x + val.y + val.z + val.w);
    float sq  = warp_sum(val.x * val.x + val.y * val.y + val.z * val.z + val.w * val.w);
    float mu = sum * (1.f / 128.f);
    float var = sq * (1.f / 128.f) - mu * mu;
    float r = rsqrtf(var + 1e-5f);
    float4 gg = *reinterpret_cast<const float4*>(g + c);
    float4 bv = *reinterpret_cast<const float4*>(bb + c);
    float4 y;
    y.x = (val.x - mu) * r * gg.x + bv.x;
    y.y = (val.y - mu) * r * gg.y + bv.y;
    y.z = (val.z - mu) * r * gg.z + bv.z;
    y.w = (val.w - mu) * r * gg.w + bv.w;
    y.x = y.x > 0.f ? y.x : expm1f(y.x);
    y.y = y.y > 0.f ? y.y : expm1f(y.y);
    y.z = y.z > 0.f ? y.z : expm1f(y.z);
    y.w = y.w > 0.f ? y.w : expm1f(y.w);
    *reinterpret_cast<float4*>(out + (size_t)warp * D + c) = y;
    float4 vd = *reinterpret_cast<const float4*>(vdst + c);
    float pdv = y.x * vd.x + y.y * vd.y + y.z * vd.z + y.w * vd.w;
    pdv = warp_sum(pdv);
    if (lane == 0) alDit[warp] = pdv;
}

// ---------------- finalize 1-head GAT ----------------
__global__ void fin1(float* __restrict__ out, const float* __restrict__ xs,
                     const float* __restrict__ alS, const float* __restrict__ alD,
                     const float* __restrict__ s, const float* __restrict__ bias,
                     int selfloop, int n) {
    int warp = (blockIdx.x * blockDim.x + threadIdx.x) >> 5;
    int lane = threadIdx.x & 31;
    if (warp >= n) return;
    int c = lane * 4;
    float ws = 0.f, inv;
    if (selfloop) {
        ws = __expf(lrelu(alS[warp] + alD[warp]));
        inv = 1.f / (s[warp] + ws + 1e-16f);
    } else {
        inv = 1.f / (s[warp] + 1e-16f);
    }
    float4 A = *reinterpret_cast<const float4*>(out + (size_t)warp * D + c);
    float4 X = *reinterpret_cast<const float4*>(xs + (size_t)warp * D + c);
    float4 Bv = *reinterpret_cast<const float4*>(bias + c);
    float4 y;
    y.x = (A.x + ws * X.x) * inv + Bv.x;
    y.y = (A.y + ws * X.y) * inv + Bv.y;
    y.z = (A.z + ws * X.z) * inv + Bv.z;
    y.w = (A.w + ws * X.w) * inv + Bv.w;
    *reinterpret_cast<float4*>(out + (size_t)warp * D + c) = y;
}

// ---------------- misc ----------------
__global__ void compute_vdst(const float* __restrict__ Wd, const float* __restrict__ ad,
                             float* v) {
    int i = threadIdx.x;
    float sum = 0.f;
    for (int j = 0; j < D; j++) sum += Wd[i * D + j] * ad[j];
    v[i] = sum;
}

// ---------------- SAG readout ----------------
__global__ void sag_edge(const int* __restrict__ src, const int* __restrict__ dst,
                         const float* __restrict__ pRel, float* attn, int E) {
    int e = blockIdx.x * blockDim.x + threadIdx.x;
    if (e >= E) return;
    atomicAdd(&attn[dst[e]], pRel[src[e]]);
}

__global__ void batch_expsum(float* attn, const int* __restrict__ batch,
                             float* sB, int n) {
    int i = blockIdx.x * blockDim.x + threadIdx.x;
    if (i >= n) return;
    float w = __expf(attn[i]);
    attn[i] = w;
    atomicAdd(&sB[batch[i]], w);
}

__global__ void emb_agg(const float* __restrict__ x, const float* __restrict__ attn,
                        const int* __restrict__ batch, const float* __restrict__ sB,
                        float* emb, int n) {
    int warp = (blockIdx.x * blockDim.x + threadIdx.x) >> 5;
    int lane = threadIdx.x & 31;
    if (warp >= n) return;
    int g = batch[warp];
    float coef = attn[warp] / (sB[g] + 1e-16f);
    int c = lane * 4;
    float4 xv = *reinterpret_cast<const float4*>(x + (size_t)warp * D + c);
    redAdd4(emb + (size_t)g * D + c, coef * xv.x, coef * xv.y, coef * xv.z, coef * xv.w);
}

// ---------------- host orchestration ----------------
extern "C" void kernel_launch(void* const* d_in, const int* in_sizes, int n_in,
                              void* d_out, int out_size) {
    const float* h_x        = (const float*)d_in[0];
    const float* t_x        = (const float*)d_in[1];
    const float* W_gat      = (const float*)d_in[2];
    const float* a_src_gat  = (const float*)d_in[3];
    const float* a_dst_gat  = (const float*)d_in[4];
    const float* b_gat      = (const float*)d_in[5];
    const float* ln_g       = (const float*)d_in[6];
    const float* ln_b       = (const float*)d_in[7];
    const float* W_intra    = (const float*)d_in[8];
    const float* a_src_in   = (const float*)d_in[9];
    const float* a_dst_in   = (const float*)d_in[10];
    const float* b_intra    = (const float*)d_in[11];
    const float* W_int_src  = (const float*)d_in[12];
    const float* W_int_dst  = (const float*)d_in[13];
    const float* a_src_it   = (const float*)d_in[14];
    const float* a_dst_it   = (const float*)d_in[15];
    const float* b_inter    = (const float*)d_in[16];
    const float* W_reduce   = (const float*)d_in[17];
    const float* b_reduce   = (const float*)d_in[18];
    const float* w_rel      = (const float*)d_in[19];
    const float* b_rel      = (const float*)d_in[20];
    const float* w_root     = (const float*)d_in[21];
    const int*   h_ei       = (const int*)d_in[22];
    const int*   t_ei       = (const int*)d_in[23];
    const int*   b_ei       = (const int*)d_in[24];
    const int*   h_batch    = (const int*)d_in[25];
    const int*   t_batch    = (const int*)d_in[26];
    (void)n_in;

    const int N = in_sizes[0] / 64;
    const int E = in_sizes[22] / 2;
    const long long B = ((long long)out_size - 6LL * N * D) / (2 * D);

    float* out = (float*)d_out;
    const size_t NT = (size_t)N * D, BT = (size_t)B * D;
    float* h_fused = out;
    float* t_fused = out + NT;
    float* h_emb   = out + 2 * NT;
    float* t_emb   = h_emb + BT;
    float* h_intra = t_emb + BT;
    float* t_intra = h_intra + NT;
    float* h_inter = t_intra + NT;
    float* t_inter = h_inter + NT;

    float *xh, *xt, *tmp, *acc, *tmp2, *acc2, *tmp3, *tmp4;
    float *alS, *alD, *s, *alS2, *alD2, *s2;
    float *alS3, *s3, *alS4, *s4, *alDit_h, *alDit_t;
    float *ew, *ew2, *vdst, *sB, *sB2;
    ushort_t *w_h, *w_l;
    cudaGetSymbolAddress((void**)&xh,   g_xh);
    cudaGetSymbolAddress((void**)&xt,   g_xt);
    cudaGetSymbolAddress((void**)&tmp,  g_tmp);
    cudaGetSymbolAddress((void**)&acc,  g_acc);
    cudaGetSymbolAddress((void**)&tmp2, g_tmp2);
    cudaGetSymbolAddress((void**)&acc2, g_acc2);
    cudaGetSymbolAddress((void**)&tmp3, g_tmp3);
    cudaGetSymbolAddress((void**)&tmp4, g_tmp4);
    cudaGetSymbolAddress((void**)&alS,  g_alS);
    cudaGetSymbolAddress((void**)&alD,  g_alD);
    cudaGetSymbolAddress((void**)&s,    g_s);
    cudaGetSymbolAddress((void**)&alS2, g_alS2);
    cudaGetSymbolAddress((void**)&alD2, g_alD2);
    cudaGetSymbolAddress((void**)&s2,   g_s2);
    cudaGetSymbolAddress((void**)&alS3, g_alS3);
    cudaGetSymbolAddress((void**)&s3,   g_s3);
    cudaGetSymbolAddress((void**)&alS4, g_alS4);
    cudaGetSymbolAddress((void**)&s4,   g_s4);
    cudaGetSymbolAddress((void**)&alDit_h, g_alDit_h);
    cudaGetSymbolAddress((void**)&alDit_t, g_alDit_t);
    cudaGetSymbolAddress((void**)&ew,   g_ew);
    cudaGetSymbolAddress((void**)&ew2,  g_ew2);
    cudaGetSymbolAddress((void**)&vdst, g_vdst);
    cudaGetSymbolAddress((void**)&sB,   g_sB);
    cudaGetSymbolAddress((void**)&sB2,  g_sB2);
    cudaGetSymbolAddress((void**)&w_h,  g_w_h);
    cudaGetSymbolAddress((void**)&w_l,  g_w_l);

    ushort_t* Wg_h = w_h;            ushort_t* Wg_l = w_l;
    ushort_t* Wi_h = w_h + 64 * D;   ushort_t* Wi_l = w_l + 64 * D;
    ushort_t* Ws_h = w_h + 192 * D;  ushort_t* Ws_l = w_l + 192 * D;
    ushort_t* Wr_h = w_h + 320 * D;  ushort_t* Wr_l = w_l + 320 * D;

    static cudaStream_t s1 = nullptr;
    static cudaEvent_t evF1, evF2, evF3, evJ1, evJ2, evJ3;
    if (!s1) {
        cudaStreamCreateWithFlags(&s1, cudaStreamNonBlocking);
        cudaEventCreateWithFlags(&evF1, cudaEventDisableTiming);
        cudaEventCreateWithFlags(&evF2, cudaEventDisableTiming);
        cudaEventCreateWithFlags(&evF3, cudaEventDisableTiming);
        cudaEventCreateWithFlags(&evJ1, cudaEventDisableTiming);
        cudaEventCreateWithFlags(&evJ2, cudaEventDisableTiming);
        cudaEventCreateWithFlags(&evJ3, cudaEventDisableTiming);
    }
    cudaStream_t s0 = 0;

    const int TB = 256;
    const int nbNodeW = (N + 7) / 8;
    const int nbNodeT = (N + TB - 1) / TB;
    const int nbEdgeT = (E + TB - 1) / TB;
    const int nbEdgeO = (E * 8 + TB - 1) / TB;   // 8 threads per edge
    const int nbGemm  = (N + 127) / 128;

    const int* h_src = h_ei;       const int* h_dst = h_ei + E;
    const int* t_src = t_ei;       const int* t_dst = t_ei + E;
    const int* b_src = b_ei;       const int* b_dst = b_ei + E;

    // ===== weight split + vdst (s0) =====
    split_all<<<(576 * 128 / 4 + TB - 1) / TB, TB, 0, s0>>>(W_gat, W_intra, W_int_src,
                                                            W_reduce, w_h, w_l);
    compute_vdst<<<1, 128, 0, s0>>>(W_int_dst, a_dst_it, vdst);

    // ===== Fork 1 =====
    cudaEventRecord(evF1, s0);
    cudaStreamWaitEvent(s1, evF1, 0);

    // --- h: stage 1 (GEMM zeroes acc in epilogue) ---
    gemm_bf3<64, 1><<<nbGemm, TB, 0, s0>>>(h_x, nullptr, Wg_h, Wg_l, nullptr, tmp, N,
                                           a_src_gat, a_dst_gat, alS, alD, s, nullptr, acc);
    edge_agg2_a<<<nbEdgeO, TB, 0, s0>>>(h_src, h_dst, alS, alD, s, tmp, acc, ew, E);
    edge_agg_b<<<nbEdgeO, TB, 0, s0>>>(h_src, h_dst, ew, tmp, acc, E);
    fin_stage1<<<nbNodeW, TB, 0, s0>>>(acc, tmp, alS, alD, s, b_gat, ln_g, ln_b, xh,
                                       vdst, alDit_h, N);
    // --- h: stage 2 (zeroes h_intra) + hoisted inter GEMM (zeroes t_inter) ---
    gemm_bf3<128, 2><<<nbGemm, TB, 0, s0>>>(xh, nullptr, Wi_h, Wi_l, nullptr, tmp, N,
                                            a_src_in, a_dst_in, alS, alD, s, nullptr, h_intra);
    gemm_bf3<128, 3><<<nbGemm, TB, 0, s0>>>(xh, nullptr, Ws_h, Ws_l, nullptr, tmp3, N,
                                            a_src_it, nullptr, alS3, nullptr, s3, nullptr, t_inter);
    edge_agg1_a<<<nbEdgeO, TB, 0, s0>>>(h_src, h_dst, alS, alD, s, tmp, h_intra, ew, E);
    edge_agg_b<<<nbEdgeO, TB, 0, s0>>>(h_src, h_dst, ew, tmp, h_intra, E);
    fin1<<<nbNodeW, TB, 0, s0>>>(h_intra, tmp, alS, alD, s, b_intra, 1, N);

    // --- t: stage 1 (zeroes acc2) ---
    gemm_bf3<64, 1><<<nbGemm, TB, 0, s1>>>(t_x, nullptr, Wg_h, Wg_l, nullptr, tmp2, N,
                                           a_src_gat, a_dst_gat, alS2, alD2, s2, nullptr, acc2);
    edge_agg2_a<<<nbEdgeO, TB, 0, s1>>>(t_src, t_dst, alS2, alD2, s2, tmp2, acc2, ew2, E);
    edge_agg_b<<<nbEdgeO, TB, 0, s1>>>(t_src, t_dst, ew2, tmp2, acc2, E);
    fin_stage1<<<nbNodeW, TB, 0, s1>>>(acc2, tmp2, alS2, alD2, s2, b_gat, ln_g, ln_b, xt,
                                       vdst, alDit_t, N);
    // --- t: stage 2 (zeroes t_intra) + hoisted inter GEMM (zeroes h_inter) ---
    gemm_bf3<128, 2><<<nbGemm, TB, 0, s1>>>(xt, nullptr, Wi_h, Wi_l, nullptr, tmp2, N,
                                            a_src_in, a_dst_in, alS2, alD2, s2, nullptr, t_intra);
    gemm_bf3<128, 3><<<nbGemm, TB, 0, s1>>>(xt, nullptr, Ws_h, Ws_l, nullptr, tmp4, N,
                                            a_src_it, nullptr, alS4, nullptr, s4, nullptr, h_inter);
    edge_agg1_a<<<nbEdgeO, TB, 0, s1>>>(t_src, t_dst, alS2, alD2, s2, tmp2, t_intra, ew2, E);
    edge_agg_b<<<nbEdgeO, TB, 0, s1>>>(t_src, t_dst, ew2, tmp2, t_intra, E);
    fin1<<<nbNodeW, TB, 0, s1>>>(t_intra, tmp2, alS2, alD2, s2, b_intra, 1, N);

    // ===== Join 1 / Fork 2 =====
    cudaEventRecord(evJ1, s1);
    cudaStreamWaitEvent(s0, evJ1, 0);
    cudaEventRecord(evF2, s0);
    cudaStreamWaitEvent(s1, evF2, 0);

    // --- s0: t_inter (already zeroed by MODE-3 GEMM on s0) ---
    edge_agg1_a<<<nbEdgeO, TB, 0, s0>>>(b_src, b_dst, alS3, alDit_t, s3, tmp3, t_inter, ew, E);
    edge_agg_b<<<nbEdgeO, TB, 0, s0>>>(b_src, b_dst, ew, tmp3, t_inter, E);
    fin1<<<nbNodeW, TB, 0, s0>>>(t_inter, tmp3, alS3, alDit_t, s3, b_inter, 0, N);

    // --- s1: h_inter (already zeroed by MODE-3 GEMM on s1) ---
    edge_agg1_a<<<nbEdgeO, TB, 0, s1>>>(b_dst, b_src, alS4, alDit_h, s4, tmp4, h_inter, ew2, E);
    edge_agg_b<<<nbEdgeO, TB, 0, s1>>>(b_dst, b_src, ew2, tmp4, h_inter, E);
    fin1<<<nbNodeW, TB, 0, s1>>>(h_inter, tmp4, alS4, alDit_h, s4, b_inter, 0, N);

    // ===== Join 2 / Fork 3 =====
    cudaEventRecord(evJ2, s1);
    cudaStreamWaitEvent(s0, evJ2, 0);
    cudaEventRecord(evF3, s0);
    cudaStreamWaitEvent(s1, evF3, 0);

    // --- s0: h side ---
    gemm_bf3<256, 4><<<nbGemm, TB, 0, s0>>>(h_intra, h_inter, Wr_h, Wr_l, b_reduce, h_fused, N,
                                            w_rel, w_root, alS, alD, nullptr, b_rel, nullptr);
    sag_edge<<<nbEdgeT, TB, 0, s0>>>(h_src, h_dst, alS, alD, E);
    cudaMemsetAsync(sB, 0, B * sizeof(float), s0);
    batch_expsum<<<nbNodeT, TB, 0, s0>>>(alD, h_batch, sB, N);
    cudaMemsetAsync(h_emb, 0, BT * sizeof(float), s0);
    emb_agg<<<nbNodeW, TB, 0, s0>>>(h_fused, alD, h_batch, sB, h_emb, N);

    // --- s1: t side ---
    gemm_bf3<256, 4><<<nbGemm, TB, 0, s1>>>(t_intra, t_inter, Wr_h, Wr_l, b_reduce, t_fused, N,
                                            w_rel, w_root, alS2, alD2, nullptr, b_rel, nullptr);
    sag_edge<<<nbEdgeT, TB, 0, s1>>>(t_src, t_dst, alS2, alD2, E);
    cudaMemsetAsync(sB2, 0, B * sizeof(float), s1);
    batch_expsum<<<nbNodeT, TB, 0, s1>>>(alD2, t_batch, sB2, N);
    cudaMemsetAsync(t_emb, 0, BT * sizeof(float), s1);
    emb_agg<<<nbNodeW, TB, 0, s1>>>(t_fused, alD2, t_batch, sB2, t_emb, N);

    // ===== Final join =====
    cudaEventRecord(evJ3, s1);
    cudaStreamWaitEvent(s0, evJ3, 0);
}

// round 17
// speedup vs baseline: 1.0495x; 1.0495x over previous
#include <cuda_runtime.h>
#include <cuda_bf16.h>
#include <math.h>

#define NMAX 200000
#define EMAX 600000
#define BMAX 10000
#define D 128

typedef unsigned short ushort_t;

// ---------------- scratch ----------------
__device__ float g_xh[NMAX * D];
__device__ float g_xt[NMAX * D];
__device__ float g_tmp[NMAX * D];
__device__ float g_acc[NMAX * D];
__device__ float g_tmp2[NMAX * D];
__device__ float g_acc2[NMAX * D];
__device__ float g_tmp3[NMAX * D];
__device__ float g_tmp4[NMAX * D];
__device__ float g_alS[NMAX * 2],  g_alD[NMAX * 2],  g_s[NMAX * 2];
__device__ float g_alS2[NMAX * 2], g_alD2[NMAX * 2], g_s2[NMAX * 2];
__device__ float g_alS3[NMAX], g_s3[NMAX];
__device__ float g_alS4[NMAX], g_s4[NMAX];
__device__ float g_alDit_h[NMAX], g_alDit_t[NMAX];
__device__ float g_ew[EMAX], g_ew2[EMAX];      // cached per-edge weights (2nd half)
__device__ float g_vdst[D];
__device__ float g_sB[BMAX], g_sB2[BMAX];
__device__ ushort_t g_w_h[576 * 128], g_w_l[576 * 128];

// ---------------- helpers ----------------
__device__ __forceinline__ float lrelu(float x) { return x > 0.f ? x : 0.2f * x; }

__device__ __forceinline__ float warp_sum(float v) {
#pragma unroll
    for (int o = 16; o > 0; o >>= 1) v += __shfl_xor_sync(0xffffffffu, v, o);
    return v;
}

__device__ __forceinline__ void mma_bf16(float* c, const unsigned* a, const unsigned* b) {
    asm volatile(
        "mma.sync.aligned.m16n8k16.row.col.f32.bf16.bf16.f32 "
        "{%0,%1,%2,%3}, {%4,%5,%6,%7}, {%8,%9}, {%0,%1,%2,%3};"
        : "+f"(c[0]), "+f"(c[1]), "+f"(c[2]), "+f"(c[3])
        : "r"(a[0]), "r"(a[1]), "r"(a[2]), "r"(a[3]), "r"(b[0]), "r"(b[1]));
}

__device__ __forceinline__ void ldsm4(unsigned* r, const void* p) {
    unsigned addr = (unsigned)__cvta_generic_to_shared(p);
    asm volatile("ldmatrix.sync.aligned.m8n8.x4.shared.b16 {%0,%1,%2,%3}, [%4];"
                 : "=r"(r[0]), "=r"(r[1]), "=r"(r[2]), "=r"(r[3]) : "r"(addr));
}

__device__ __forceinline__ void ldsm4t(unsigned* r, const void* p) {
    unsigned addr = (unsigned)__cvta_generic_to_shared(p);
    asm volatile("ldmatrix.sync.aligned.m8n8.x4.trans.shared.b16 {%0,%1,%2,%3}, [%4];"
                 : "=r"(r[0]), "=r"(r[1]), "=r"(r[2]), "=r"(r[3]) : "r"(addr));
}

__device__ __forceinline__ void redAdd4(float* p, float x, float y, float z, float w) {
    asm volatile("red.global.add.v4.f32 [%0], {%1,%2,%3,%4};"
                 :: "l"(p), "f"(x), "f"(y), "f"(z), "f"(w) : "memory");
}

__device__ __forceinline__ void split1(float a, ushort_t& h, ushort_t& l) {
    __nv_bfloat16 ah = __float2bfloat16(a);
    h = __bfloat16_as_ushort(ah);
    l = __bfloat16_as_ushort(__float2bfloat16(a - __bfloat162float(ah)));
}

__device__ __forceinline__ void split2(float a, float b, unsigned& hi, unsigned& lo) {
    ushort_t ha, la, hb, lb;
    split1(a, ha, la);
    split1(b, hb, lb);
    hi = (unsigned)ha | ((unsigned)hb << 16);
    lo = (unsigned)la | ((unsigned)lb << 16);
}

// ---------------- single-launch weight split ----------------
__global__ void split_all(const float* __restrict__ Wg, const float* __restrict__ Wi,
                          const float* __restrict__ Ws, const float* __restrict__ Wr,
                          ushort_t* __restrict__ H, ushort_t* __restrict__ L) {
    int i = blockIdx.x * blockDim.x + threadIdx.x;
    if (i >= 576 * 128 / 4) return;
    int base = i * 4;
    const float* src;
    int off;
    if (base < 64 * 128)        { src = Wg; off = base; }
    else if (base < 192 * 128)  { src = Wi; off = base - 64 * 128; }
    else if (base < 320 * 128)  { src = Ws; off = base - 192 * 128; }
    else                        { src = Wr; off = base - 320 * 128; }
    float4 v = *reinterpret_cast<const float4*>(src + off);
    unsigned h01, l01, h23, l23;
    split2(v.x, v.y, h01, l01);
    split2(v.z, v.w, h23, l23);
    *reinterpret_cast<uint2*>(H + base) = make_uint2(h01, h23);
    *reinterpret_cast<uint2*>(L + base) = make_uint2(l01, l23);
}

// ---------------- bf16x3 GEMM with fused node-prep epilogue ----------------
// MODE 0: plain.  MODE 1: 2-head prep.  MODE 2: 1-head both dots.
// MODE 3: 1-head aS only.  MODE 4: SAG prep.
template <int K, int MODE>
__global__ void __launch_bounds__(256, 2)
gemm_bf3(const float* __restrict__ A0, const float* __restrict__ A1,
         const ushort_t* __restrict__ Wh, const ushort_t* __restrict__ Wl,
         const float* __restrict__ bias, float* __restrict__ C, int n,
         const float* __restrict__ aS, const float* __restrict__ aD,
         float* __restrict__ oS, float* __restrict__ oD,
         float* __restrict__ sArr, const float* __restrict__ brel) {
    __shared__ __align__(16) ushort_t sAh[128][40], sAl[128][40];
    __shared__ __align__(16) ushort_t sBh[32][136], sBl[32][136];
    __shared__ float sRed[128][2][2];
    const int row0 = blockIdx.x * 128;
    const int tid = threadIdx.x;
    const int warp = tid >> 5, lane = tid & 31;
    const int wm = warp >> 1, wn = warp & 1;
    const int g = lane >> 2, tig = lane & 3;
    const int l15 = lane & 15, l16o = ((lane >> 4) & 1) * 8;

    float acc[2][8][4];
#pragma unroll
    for (int mt = 0; mt < 2; mt++)
#pragma unroll
        for (int nt = 0; nt < 8; nt++)
#pragma unroll
            for (int v = 0; v < 4; v++) acc[mt][nt][v] = 0.f;

    for (int k0 = 0; k0 < K; k0 += 32) {
        const float* Abase;
        int kloc, stride;
        if (K == 256) { Abase = (k0 < 128) ? A0 : A1; kloc = k0 & 127; stride = 128; }
        else          { Abase = A0; kloc = k0; stride = K; }
#pragma unroll
        for (int i = 0; i < 4; i++) {
            int L = i * 256 + tid;
            int r = L >> 3, kc = (L & 7) << 2;
            float4 v = make_float4(0.f, 0.f, 0.f, 0.f);
            int gr = row0 + r;
            if (gr < n) v = *reinterpret_cast<const float4*>(Abase + (size_t)gr * stride + kloc + kc);
            unsigned h01, l01, h23, l23;
            split2(v.x, v.y, h01, l01);
            split2(v.z, v.w, h23, l23);
            *reinterpret_cast<uint2*>(&sAh[r][kc]) = make_uint2(h01, h23);
            *reinterpret_cast<uint2*>(&sAl[r][kc]) = make_uint2(l01, l23);
        }
#pragma unroll
        for (int i = 0; i < 2; i++) {
            int L = i * 256 + tid;
            int r = L >> 4, c8 = (L & 15) * 8;
            *reinterpret_cast<uint4*>(&sBh[r][c8]) =
                *reinterpret_cast<const uint4*>(Wh + (size_t)(k0 + r) * D + c8);
            *reinterpret_cast<uint4*>(&sBl[r][c8]) =
                *reinterpret_cast<const uint4*>(Wl + (size_t)(k0 + r) * D + c8);
        }
        __syncthreads();
#pragma unroll
        for (int kk = 0; kk < 32; kk += 16) {
            unsigned ah[2][4], al[2][4];
#pragma unroll
            for (int mt = 0; mt < 2; mt++) {
                int ar = wm * 32 + mt * 16 + l15;
                ldsm4(ah[mt], &sAh[ar][kk + l16o]);
                ldsm4(al[mt], &sAl[ar][kk + l16o]);
            }
            int br = kk + l15;
#pragma unroll
            for (int h2 = 0; h2 < 2; h2++) {
                unsigned bh[4][2], bl[4][2], t4[4];
#pragma unroll
                for (int p = 0; p < 2; p++) {
                    int bc = wn * 64 + h2 * 32 + p * 16 + l16o;
                    ldsm4t(t4, &sBh[br][bc]);
                    bh[2 * p][0] = t4[0]; bh[2 * p][1] = t4[1];
                    bh[2 * p + 1][0] = t4[2]; bh[2 * p + 1][1] = t4[3];
                    ldsm4t(t4, &sBl[br][bc]);
                    bl[2 * p][0] = t4[0]; bl[2 * p][1] = t4[1];
                    bl[2 * p + 1][0] = t4[2]; bl[2 * p + 1][1] = t4[3];
                }
#pragma unroll
                for (int mt = 0; mt < 2; mt++)
#pragma unroll
                    for (int nt = 0; nt < 4; nt++) {
                        float* c = acc[mt][h2 * 4 + nt];
                        mma_bf16(c, al[mt], bh[nt]);
                        mma_bf16(c, ah[mt], bl[nt]);
                        mma_bf16(c, ah[mt], bh[nt]);
                    }
            }
        }
        __syncthreads();
    }

    float pS[4] = {0.f, 0.f, 0.f, 0.f};
    float pD[4] = {0.f, 0.f, 0.f, 0.f};

#pragma unroll
    for (int mt = 0; mt < 2; mt++) {
        int r0 = row0 + wm * 32 + mt * 16 + g;
        int r1 = r0 + 8;
#pragma unroll
        for (int nt = 0; nt < 8; nt++) {
            int c = wn * 64 + nt * 8 + 2 * tig;
            float b0 = 0.f, b1 = 0.f;
            if (bias) { b0 = __ldg(bias + c); b1 = __ldg(bias + c + 1); }
            float v0 = acc[mt][nt][0] + b0, v1 = acc[mt][nt][1] + b1;
            float v2 = acc[mt][nt][2] + b0, v3 = acc[mt][nt][3] + b1;
            if (MODE) {
                float a0 = __ldg(aS + c), a1 = __ldg(aS + c + 1);
                pS[mt * 2 + 0] += v0 * a0 + v1 * a1;
                pS[mt * 2 + 1] += v2 * a0 + v3 * a1;
                if (MODE != 3) {
                    float d0 = __ldg(aD + c), d1 = __ldg(aD + c + 1);
                    pD[mt * 2 + 0] += v0 * d0 + v1 * d1;
                    pD[mt * 2 + 1] += v2 * d0 + v3 * d1;
                }
            }
            if (r0 < n) { float* cp = C + (size_t)r0 * D + c; cp[0] = v0; cp[1] = v1; }
            if (r1 < n) { float* cp = C + (size_t)r1 * D + c; cp[0] = v2; cp[1] = v3; }
        }
    }

    if (MODE) {
#pragma unroll
        for (int i = 0; i < 4; i++) {
            pS[i] += __shfl_down_sync(0xffffffffu, pS[i], 2);
            pS[i] += __shfl_down_sync(0xffffffffu, pS[i], 1);
            if (MODE != 3) {
                pD[i] += __shfl_down_sync(0xffffffffu, pD[i], 2);
                pD[i] += __shfl_down_sync(0xffffffffu, pD[i], 1);
            }
        }
        if (MODE == 1) {
            if (tig == 0) {
#pragma unroll
                for (int i = 0; i < 4; i++) {
                    int r = wm * 32 + (i >> 1) * 16 + g + (i & 1) * 8;
                    int gr = row0 + r;
                    if (gr < n) {
                        oS[gr * 2 + wn] = pS[i];
                        oD[gr * 2 + wn] = pD[i];
                        sArr[gr * 2 + wn] = 0.f;
                    }
                }
            }
        } else {
            if (tig == 0) {
#pragma unroll
                for (int i = 0; i < 4; i++) {
                    int r = wm * 32 + (i >> 1) * 16 + g + (i & 1) * 8;
                    sRed[r][0][wn] = pS[i];
                    if (MODE != 3) sRed[r][1][wn] = pD[i];
                }
            }
            __syncthreads();
            if (tid < 128) {
                int gr = row0 + tid;
                if (gr < n) {
                    float S = sRed[tid][0][0] + sRed[tid][0][1];
                    oS[gr] = S;
                    if (MODE == 2) {
                        oD[gr] = sRed[tid][1][0] + sRed[tid][1][1];
                        sArr[gr] = 0.f;
                    } else if (MODE == 3) {
                        sArr[gr] = 0.f;
                    } else {
                        oD[gr] = sRed[tid][1][0] + sRed[tid][1][1] + __ldg(brel);
                    }
                }
            }
        }
    }
}

// ---------------- edge aggregate: 8 lanes/edge, 2 float4/thread, w-cached ----------------
__global__ void edge_agg2_a(const int* __restrict__ src, const int* __restrict__ dst,
                            const float* __restrict__ alS, const float* __restrict__ alD,
                            float* s, const float* __restrict__ xs, float* acc,
                            float* __restrict__ ew, int E) {
    int t = blockIdx.x * blockDim.x + threadIdx.x;
    int e = t >> 3;
    if (e >= E) return;
    int lane = threadIdx.x & 31;
    int sub = lane & 7, base = lane & ~7;
    int u = 0, v = 0;
    if (sub == 0) { u = src[e]; v = dst[e]; }
    u = __shfl_sync(0xffffffffu, u, base);
    v = __shfl_sync(0xffffffffu, v, base);
    float w0 = 0.f;
    if (sub == 0) {
        float2 aS = *reinterpret_cast<const float2*>(alS + u * 2);
        float2 aD = *reinterpret_cast<const float2*>(alD + v * 2);
        w0 = __expf(lrelu(aS.x + aD.x));
        float w1 = __expf(lrelu(aS.y + aD.y));
        atomicAdd(&s[v * 2 + 0], w0);
        atomicAdd(&s[v * 2 + 1], w1);
        ew[e] = w1;
    }
    w0 = __shfl_sync(0xffffffffu, w0, base);
    int c = sub * 4;
    const float* xp = xs + (size_t)u * D;
    float4 x0 = *reinterpret_cast<const float4*>(xp + c);
    float4 x1 = *reinterpret_cast<const float4*>(xp + c + 32);
    float* ap = acc + (size_t)v * D;
    redAdd4(ap + c,      w0 * x0.x, w0 * x0.y, w0 * x0.z, w0 * x0.w);
    redAdd4(ap + c + 32, w0 * x1.x, w0 * x1.y, w0 * x1.z, w0 * x1.w);
}

__global__ void edge_agg_b(const int* __restrict__ src, const int* __restrict__ dst,
                           const float* __restrict__ ew, const float* __restrict__ xs,
                           float* acc, int E) {
    int t = blockIdx.x * blockDim.x + threadIdx.x;
    int e = t >> 3;
    if (e >= E) return;
    int lane = threadIdx.x & 31;
    int sub = lane & 7, base = lane & ~7;
    int u = 0, v = 0;
    if (sub == 0) { u = src[e]; v = dst[e]; }
    u = __shfl_sync(0xffffffffu, u, base);
    v = __shfl_sync(0xffffffffu, v, base);
    float w = ew[e];
    int c = 64 + sub * 4;
    const float* xp = xs + (size_t)u * D;
    float4 x0 = *reinterpret_cast<const float4*>(xp + c);
    float4 x1 = *reinterpret_cast<const float4*>(xp + c + 32);
    float* ap = acc + (size_t)v * D;
    redAdd4(ap + c,      w * x0.x, w * x0.y, w * x0.z, w * x0.w);
    redAdd4(ap + c + 32, w * x1.x, w * x1.y, w * x1.z, w * x1.w);
}

__global__ void edge_agg1_a(const int* __restrict__ src, const int* __restrict__ dst,
                            const float* __restrict__ alS, const float* __restrict__ alD,
                            float* s, const float* __restrict__ xs, float* acc,
                            float* __restrict__ ew, int E) {
    int t = blockIdx.x * blockDim.x + threadIdx.x;
    int e = t >> 3;
    if (e >= E) return;
    int lane = threadIdx.x & 31;
    int sub = lane & 7, base = lane & ~7;
    int u = 0, v = 0;
    if (sub == 0) { u = src[e]; v = dst[e]; }
    u = __shfl_sync(0xffffffffu, u, base);
    v = __shfl_sync(0xffffffffu, v, base);
    float w = 0.f;
    if (sub == 0) {
        w = __expf(lrelu(alS[u] + alD[v]));
        atomicAdd(&s[v], w);
        ew[e] = w;
    }
    w = __shfl_sync(0xffffffffu, w, base);
    int c = sub * 4;
    const float* xp = xs + (size_t)u * D;
    float4 x0 = *reinterpret_cast<const float4*>(xp + c);
    float4 x1 = *reinterpret_cast<const float4*>(xp + c + 32);
    float* ap = acc + (size_t)v * D;
    redAdd4(ap + c,      w * x0.x, w * x0.y, w * x0.z, w * x0.w);
    redAdd4(ap + c + 32, w * x1.x, w * x1.y, w * x1.z, w * x1.w);
}

// ---------------- finalize stage 1 (+ fused inter dst-logit) ----------------
__global__ void fin_stage1(const float* __restrict__ acc, const float* __restrict__ xs,
                           const float* __restrict__ alS, const float* __restrict__ alD,
                           const float* __restrict__ s,
                           const float* __restrict__ bgat, const float* __restrict__ g,
                           const float* __restrict__ bb, float* __restrict__ out,
                           const float* __restrict__ vdst, float* __restrict__ alDit,
                           int n) {
    int warp = (blockIdx.x * blockDim.x + threadIdx.x) >> 5;
    int lane = threadIdx.x & 31;
    if (warp >= n) return;
    int h = lane >> 4;
    int c = lane * 4;
    float e  = lrelu(alS[warp * 2 + h] + alD[warp * 2 + h]);
    float ws = __expf(e);
    float inv = 1.f / (s[warp * 2 + h] + ws + 1e-16f);
    float4 A = *reinterpret_cast<const float4*>(acc + (size_t)warp * D + c);
    float4 X = *reinterpret_cast<const float4*>(xs + (size_t)warp * D + c);
    float4 Bt = *reinterpret_cast<const float4*>(bgat + c);
    float4 val;
    val.x = (A.x + ws * X.x) * inv + Bt.x;
    val.y = (A.y + ws * X.y) * inv + Bt.y;
    val.z = (A.z + ws * X.z) * inv + Bt.z;
    val.w = (A.w + ws * X.w) * inv + Bt.w;
    float sum = warp_sum(val.x + val.y + val.z + val.w);
    float sq  = warp_sum(val.x * val.x + val.y * val.y + val.z * val.z + val.w * val.w);
    float mu = sum * (1.f / 128.f);
    float var = sq * (1.f / 128.f) - mu * mu;
    float r = rsqrtf(var + 1e-5f);
    float4 gg = *reinterpret_cast<const float4*>(g + c);
    float4 bv = *reinterpret_cast<const float4*>(bb + c);
    float4 y;
    y.x = (val.x - mu) * r * gg.x + bv.x;
    y.y = (val.y - mu) * r * gg.y + bv.y;
    y.z = (val.z - mu) * r * gg.z + bv.z;
    y.w = (val.w - mu) * r * gg.w + bv.w;
    y.x = y.x > 0.f ? y.x : expm1f(y.x);
    y.y = y.y > 0.f ? y.y : expm1f(y.y);
    y.z = y.z > 0.f ? y.z : expm1f(y.z);
    y.w = y.w > 0.f ? y.w : expm1f(y.w);
    *reinterpret_cast<float4*>(out + (size_t)warp * D + c) = y;
    float4 vd = *reinterpret_cast<const float4*>(vdst + c);
    float pdv = y.x * vd.x + y.y * vd.y + y.z * vd.z + y.w * vd.w;
    pdv = warp_sum(pdv);
    if (lane == 0) alDit[warp] = pdv;
}

// ---------------- finalize 1-head GAT ----------------
__global__ void fin1(float* __restrict__ out, const float* __restrict__ xs,
                     const float* __restrict__ alS, const float* __restrict__ alD,
                     const float* __restrict__ s, const float* __restrict__ bias,
                     int selfloop, int n) {
    int warp = (blockIdx.x * blockDim.x + threadIdx.x) >> 5;
    int lane = threadIdx.x & 31;
    if (warp >= n) return;
    int c = lane * 4;
    float ws = 0.f, inv;
    if (selfloop) {
        ws = __expf(lrelu(alS[warp] + alD[warp]));
        inv = 1.f / (s[warp] + ws + 1e-16f);
    } else {
        inv = 1.f / (s[warp] + 1e-16f);
    }
    float4 A = *reinterpret_cast<const float4*>(out + (size_t)warp * D + c);
    float4 X = *reinterpret_cast<const float4*>(xs + (size_t)warp * D + c);
    float4 Bv = *reinterpret_cast<const float4*>(bias + c);
    float4 y;
    y.x = (A.x + ws * X.x) * inv + Bv.x;
    y.y = (A.y + ws * X.y) * inv + Bv.y;
    y.z = (A.z + ws * X.z) * inv + Bv.z;
    y.w = (A.w + ws * X.w) * inv + Bv.w;
    *reinterpret_cast<float4*>(out + (size_t)warp * D + c) = y;
}

// ---------------- misc ----------------
__global__ void compute_vdst(const float* __restrict__ Wd, const float* __restrict__ ad,
                             float* v) {
    int i = threadIdx.x;
    float sum = 0.f;
    for (int j = 0; j < D; j++) sum += Wd[i * D + j] * ad[j];
    v[i] = sum;
}

// ---------------- SAG readout ----------------
__global__ void sag_edge(const int* __restrict__ src, const int* __restrict__ dst,
                         const float* __restrict__ pRel, float* attn, int E) {
    int e = blockIdx.x * blockDim.x + threadIdx.x;
    if (e >= E) return;
    atomicAdd(&attn[dst[e]], pRel[src[e]]);
}

__global__ void batch_expsum(float* attn, const int* __restrict__ batch,
                             float* sB, int n) {
    int i = blockIdx.x * blockDim.x + threadIdx.x;
    if (i >= n) return;
    float w = __expf(attn[i]);
    attn[i] = w;
    atomicAdd(&sB[batch[i]], w);
}

__global__ void emb_agg(const float* __restrict__ x, const float* __restrict__ attn,
                        const int* __restrict__ batch, const float* __restrict__ sB,
                        float* emb, int n) {
    int warp = (blockIdx.x * blockDim.x + threadIdx.x) >> 5;
    int lane = threadIdx.x & 31;
    if (warp >= n) return;
    int g = batch[warp];
    float coef = attn[warp] / (sB[g] + 1e-16f);
    int c = lane * 4;
    float4 xv = *reinterpret_cast<const float4*>(x + (size_t)warp * D + c);
    redAdd4(emb + (size_t)g * D + c, coef * xv.x, coef * xv.y, coef * xv.z, coef * xv.w);
}

// ---------------- host orchestration ----------------
extern "C" void kernel_launch(void* const* d_in, const int* in_sizes, int n_in,
                              void* d_out, int out_size) {
    const float* h_x        = (const float*)d_in[0];
    const float* t_x        = (const float*)d_in[1];
    const float* W_gat      = (const float*)d_in[2];
    const float* a_src_gat  = (const float*)d_in[3];
    const float* a_dst_gat  = (const float*)d_in[4];
    const float* b_gat      = (const float*)d_in[5];
    const float* ln_g       = (const float*)d_in[6];
    const float* ln_b       = (const float*)d_in[7];
    const float* W_intra    = (const float*)d_in[8];
    const float* a_src_in   = (const float*)d_in[9];
    const float* a_dst_in   = (const float*)d_in[10];
    const float* b_intra    = (const float*)d_in[11];
    const float* W_int_src  = (const float*)d_in[12];
    const float* W_int_dst  = (const float*)d_in[13];
    const float* a_src_it   = (const float*)d_in[14];
    const float* a_dst_it   = (const float*)d_in[15];
    const float* b_inter    = (const float*)d_in[16];
    const float* W_reduce   = (const float*)d_in[17];
    const float* b_reduce   = (const float*)d_in[18];
    const float* w_rel      = (const float*)d_in[19];
    const float* b_rel      = (const float*)d_in[20];
    const float* w_root     = (const float*)d_in[21];
    const int*   h_ei       = (const int*)d_in[22];
    const int*   t_ei       = (const int*)d_in[23];
    const int*   b_ei       = (const int*)d_in[24];
    const int*   h_batch    = (const int*)d_in[25];
    const int*   t_batch    = (const int*)d_in[26];
    (void)n_in;

    const int N = in_sizes[0] / 64;
    const int E = in_sizes[22] / 2;
    const long long B = ((long long)out_size - 6LL * N * D) / (2 * D);

    float* out = (float*)d_out;
    const size_t NT = (size_t)N * D, BT = (size_t)B * D;
    float* h_fused = out;
    float* t_fused = out + NT;
    float* h_emb   = out + 2 * NT;
    float* t_emb   = h_emb + BT;
    float* h_intra = t_emb + BT;
    float* t_intra = h_intra + NT;
    float* h_inter = t_intra + NT;
    float* t_inter = h_inter + NT;

    float *xh, *xt, *tmp, *acc, *tmp2, *acc2, *tmp3, *tmp4;
    float *alS, *alD, *s, *alS2, *alD2, *s2;
    float *alS3, *s3, *alS4, *s4, *alDit_h, *alDit_t;
    float *ew, *ew2, *vdst, *sB, *sB2;
    ushort_t *w_h, *w_l;
    cudaGetSymbolAddress((void**)&xh,   g_xh);
    cudaGetSymbolAddress((void**)&xt,   g_xt);
    cudaGetSymbolAddress((void**)&tmp,  g_tmp);
    cudaGetSymbolAddress((void**)&acc,  g_acc);
    cudaGetSymbolAddress((void**)&tmp2, g_tmp2);
    cudaGetSymbolAddress((void**)&acc2, g_acc2);
    cudaGetSymbolAddress((void**)&tmp3, g_tmp3);
    cudaGetSymbolAddress((void**)&tmp4, g_tmp4);
    cudaGetSymbolAddress((void**)&alS,  g_alS);
    cudaGetSymbolAddress((void**)&alD,  g_alD);
    cudaGetSymbolAddress((void**)&s,    g_s);
    cudaGetSymbolAddress((void**)&alS2, g_alS2);
    cudaGetSymbolAddress((void**)&alD2, g_alD2);
    cudaGetSymbolAddress((void**)&s2,   g_s2);
    cudaGetSymbolAddress((void**)&alS3, g_alS3);
    cudaGetSymbolAddress((void**)&s3,   g_s3);
    cudaGetSymbolAddress((void**)&alS4, g_alS4);
    cudaGetSymbolAddress((void**)&s4,   g_s4);
    cudaGetSymbolAddress((void**)&alDit_h, g_alDit_h);
    cudaGetSymbolAddress((void**)&alDit_t, g_alDit_t);
    cudaGetSymbolAddress((void**)&ew,   g_ew);
    cudaGetSymbolAddress((void**)&ew2,  g_ew2);
    cudaGetSymbolAddress((void**)&vdst, g_vdst);
    cudaGetSymbolAddress((void**)&sB,   g_sB);
    cudaGetSymbolAddress((void**)&sB2,  g_sB2);
    cudaGetSymbolAddress((void**)&w_h,  g_w_h);
    cudaGetSymbolAddress((void**)&w_l,  g_w_l);

    ushort_t* Wg_h = w_h;            ushort_t* Wg_l = w_l;
    ushort_t* Wi_h = w_h + 64 * D;   ushort_t* Wi_l = w_l + 64 * D;
    ushort_t* Ws_h = w_h + 192 * D;  ushort_t* Ws_l = w_l + 192 * D;
    ushort_t* Wr_h = w_h + 320 * D;  ushort_t* Wr_l = w_l + 320 * D;

    static cudaStream_t s1 = nullptr;
    static cudaEvent_t evF1, evF2, evF3, evJ1, evJ2, evJ3;
    if (!s1) {
        cudaStreamCreateWithFlags(&s1, cudaStreamNonBlocking);
        cudaEventCreateWithFlags(&evF1, cudaEventDisableTiming);
        cudaEventCreateWithFlags(&evF2, cudaEventDisableTiming);
        cudaEventCreateWithFlags(&evF3, cudaEventDisableTiming);
        cudaEventCreateWithFlags(&evJ1, cudaEventDisableTiming);
        cudaEventCreateWithFlags(&evJ2, cudaEventDisableTiming);
        cudaEventCreateWithFlags(&evJ3, cudaEventDisableTiming);
    }
    cudaStream_t s0 = 0;

    const int TB = 256;
    const int nbNodeW = (N + 7) / 8;
    const int nbNodeT = (N + TB - 1) / TB;
    const int nbEdgeT = (E + TB - 1) / TB;
    const int nbEdgeO = (E * 8 + TB - 1) / TB;   // 8 threads per edge
    const int nbGemm  = (N + 127) / 128;

    const int* h_src = h_ei;       const int* h_dst = h_ei + E;
    const int* t_src = t_ei;       const int* t_dst = t_ei + E;
    const int* b_src = b_ei;       const int* b_dst = b_ei + E;

    // ===== weight split + vdst (s0) =====
    split_all<<<(576 * 128 / 4 + TB - 1) / TB, TB, 0, s0>>>(W_gat, W_intra, W_int_src,
                                                            W_reduce, w_h, w_l);
    compute_vdst<<<1, 128, 0, s0>>>(W_int_dst, a_dst_it, vdst);

    // ===== Fork 1 =====
    cudaEventRecord(evF1, s0);
    cudaStreamWaitEvent(s1, evF1, 0);

    // --- h: stage 1 ---
    gemm_bf3<64, 1><<<nbGemm, TB, 0, s0>>>(h_x, nullptr, Wg_h, Wg_l, nullptr, tmp, N,
                                           a_src_gat, a_dst_gat, alS, alD, s, nullptr);
    cudaMemsetAsync(acc, 0, NT * sizeof(float), s0);
    edge_agg2_a<<<nbEdgeO, TB, 0, s0>>>(h_src, h_dst, alS, alD, s, tmp, acc, ew, E);
    edge_agg_b<<<nbEdgeO, TB, 0, s0>>>(h_src, h_dst, ew, tmp, acc, E);
    fin_stage1<<<nbNodeW, TB, 0, s0>>>(acc, tmp, alS, alD, s, b_gat, ln_g, ln_b, xh,
                                       vdst, alDit_h, N);
    // --- h: stage 2 + hoisted inter GEMM ---
    gemm_bf3<128, 2><<<nbGemm, TB, 0, s0>>>(xh, nullptr, Wi_h, Wi_l, nullptr, tmp, N,
                                            a_src_in, a_dst_in, alS, alD, s, nullptr);
    gemm_bf3<128, 3><<<nbGemm, TB, 0, s0>>>(xh, nullptr, Ws_h, Ws_l, nullptr, tmp3, N,
                                            a_src_it, nullptr, alS3, nullptr, s3, nullptr);
    cudaMemsetAsync(h_intra, 0, NT * sizeof(float), s0);
    edge_agg1_a<<<nbEdgeO, TB, 0, s0>>>(h_src, h_dst, alS, alD, s, tmp, h_intra, ew, E);
    edge_agg_b<<<nbEdgeO, TB, 0, s0>>>(h_src, h_dst, ew, tmp, h_intra, E);
    fin1<<<nbNodeW, TB, 0, s0>>>(h_intra, tmp, alS, alD, s, b_intra, 1, N);

    // --- t: stage 1 ---
    gemm_bf3<64, 1><<<nbGemm, TB, 0, s1>>>(t_x, nullptr, Wg_h, Wg_l, nullptr, tmp2, N,
                                           a_src_gat, a_dst_gat, alS2, alD2, s2, nullptr);
    cudaMemsetAsync(acc2, 0, NT * sizeof(float), s1);
    edge_agg2_a<<<nbEdgeO, TB, 0, s1>>>(t_src, t_dst, alS2, alD2, s2, tmp2, acc2, ew2, E);
    edge_agg_b<<<nbEdgeO, TB, 0, s1>>>(t_src, t_dst, ew2, tmp2, acc2, E);
    fin_stage1<<<nbNodeW, TB, 0, s1>>>(acc2, tmp2, alS2, alD2, s2, b_gat, ln_g, ln_b, xt,
                                       vdst, alDit_t, N);
    // --- t: stage 2 + hoisted inter GEMM ---
    gemm_bf3<128, 2><<<nbGemm, TB, 0, s1>>>(xt, nullptr, Wi_h, Wi_l, nullptr, tmp2, N,
                                            a_src_in, a_dst_in, alS2, alD2, s2, nullptr);
    gemm_bf3<128, 3><<<nbGemm, TB, 0, s1>>>(xt, nullptr, Ws_h, Ws_l, nullptr, tmp4, N,
                                            a_src_it, nullptr, alS4, nullptr, s4, nullptr);
    cudaMemsetAsync(t_intra, 0, NT * sizeof(float), s1);
    edge_agg1_a<<<nbEdgeO, TB, 0, s1>>>(t_src, t_dst, alS2, alD2, s2, tmp2, t_intra, ew2, E);
    edge_agg_b<<<nbEdgeO, TB, 0, s1>>>(t_src, t_dst, ew2, tmp2, t_intra, E);
    fin1<<<nbNodeW, TB, 0, s1>>>(t_intra, tmp2, alS2, alD2, s2, b_intra, 1, N);

    // ===== Join 1 / Fork 2 =====
    cudaEventRecord(evJ1, s1);
    cudaStreamWaitEvent(s0, evJ1, 0);
    cudaEventRecord(evF2, s0);
    cudaStreamWaitEvent(s1, evF2, 0);

    // --- s0: t_inter ---
    cudaMemsetAsync(t_inter, 0, NT * sizeof(float), s0);
    edge_agg1_a<<<nbEdgeO, TB, 0, s0>>>(b_src, b_dst, alS3, alDit_t, s3, tmp3, t_inter, ew, E);
    edge_agg_b<<<nbEdgeO, TB, 0, s0>>>(b_src, b_dst, ew, tmp3, t_inter, E);
    fin1<<<nbNodeW, TB, 0, s0>>>(t_inter, tmp3, alS3, alDit_t, s3, b_inter, 0, N);

    // --- s1: h_inter ---
    cudaMemsetAsync(h_inter, 0, NT * sizeof(float), s1);
    edge_agg1_a<<<nbEdgeO, TB, 0, s1>>>(b_dst, b_src, alS4, alDit_h, s4, tmp4, h_inter, ew2, E);
    edge_agg_b<<<nbEdgeO, TB, 0, s1>>>(b_dst, b_src, ew2, tmp4, h_inter, E);
    fin1<<<nbNodeW, TB, 0, s1>>>(h_inter, tmp4, alS4, alDit_h, s4, b_inter, 0, N);

    // ===== Join 2 / Fork 3 =====
    cudaEventRecord(evJ2, s1);
    cudaStreamWaitEvent(s0, evJ2, 0);
    cudaEventRecord(evF3, s0);
    cudaStreamWaitEvent(s1, evF3, 0);

    // --- s0: h side (memsets hoisted ahead of GEMM to overlap) ---
    cudaMemsetAsync(sB, 0, B * sizeof(float), s0);
    cudaMemsetAsync(h_emb, 0, BT * sizeof(float), s0);
    gemm_bf3<256, 4><<<nbGemm, TB, 0, s0>>>(h_intra, h_inter, Wr_h, Wr_l, b_reduce, h_fused, N,
                                            w_rel, w_root, alS, alD, nullptr, b_rel);
    sag_edge<<<nbEdgeT, TB, 0, s0>>>(h_src, h_dst, alS, alD, E);
    batch_expsum<<<nbNodeT, TB, 0, s0>>>(alD, h_batch, sB, N);
    emb_agg<<<nbNodeW, TB, 0, s0>>>(h_fused, alD, h_batch, sB, h_emb, N);

    // --- s1: t side ---
    cudaMemsetAsync(sB2, 0, B * sizeof(float), s1);
    cudaMemsetAsync(t_emb, 0, BT * sizeof(float), s1);
    gemm_bf3<256, 4><<<nbGemm, TB, 0, s1>>>(t_intra, t_inter, Wr_h, Wr_l, b_reduce, t_fused, N,
                                            w_rel, w_root, alS2, alD2, nullptr, b_rel);
    sag_edge<<<nbEdgeT, TB, 0, s1>>>(t_src, t_dst, alS2, alD2, E);
    batch_expsum<<<nbNodeT, TB, 0, s1>>>(alD2, t_batch, sB2, N);
    emb_agg<<<nbNodeW, TB, 0, s1>>>(t_fused, alD2, t_batch, sB2, t_emb, N);

    // ===== Final join =====
    cudaEventRecord(evJ3, s1);
    cudaStreamWaitEvent(s0, evJ3, 0);
}